// round 2
// baseline (speedup 1.0000x reference)
#include <cuda_runtime.h>
#include <cuda_bf16.h>
#include <cstdint>

#define NV 1000000
#define KK 27
#define NBLK 977           // ceil(NV/1024)
#define CNT_GRID 3907      // ceil(NV/256)

// ---------------- scratch (static device globals; no allocation) ----------------
__device__ float    g_t1[NV * 32];      // conv1 out [N,32]
__device__ float    g_t5[NV * 32];      // conv5 out [N,32]
__device__ float    g_a[NV * 8];        // small ping
__device__ float    g_b[NV * 8];        // small pong
__device__ unsigned g_entries[NV * KK]; // packed (k<<20)|nbr, CSR by voxel
__device__ int      g_cnt[NV];
__device__ int      g_rowloc[NV];
__device__ int      g_rowoff[NV + 1];
__device__ int      g_bsum[1024];
__device__ int      g_bscan[1024];
__device__ float    g_w1f[KK * 8 * 32]; // folded Wd0 (tile(x,4) absorbed)
__device__ int      g_maskmode;         // 0 = 1-byte elems, 1 = 4-byte elems

// ---------------- mask dtype probe (graph-safe, deterministic) ----------------
// Scans first 4MB of the mask buffer (valid for any elem size >= 1B since the
// buffer holds 27M elements). If any nonzero byte sits at offset j%4 != 0, the
// elements are 1-byte (bool/uint8). Otherwise 4-byte (int32/float32), for which
// truthiness == (32-bit word != 0).
__global__ void detect_mask(const unsigned char* __restrict__ m) {
    __shared__ int s_any;
    if (threadIdx.x == 0) s_any = 0;
    __syncthreads();
    int any = 0;
    for (int j = threadIdx.x; j < 4000000; j += blockDim.x) {
        if ((j & 3) != 0 && m[j] != 0) any = 1;
    }
    if (any) atomicOr(&s_any, 1);
    __syncthreads();
    if (threadIdx.x == 0) g_maskmode = s_any ? 0 : 1;
}

__device__ __forceinline__ bool mask_at(const unsigned char* m, long long e, int mode) {
    if (mode == 0) return m[e] != 0;
    return ((const unsigned*)m)[e] != 0u;
}

// ---------------- prep: fold Wd0 over the channel tiling ----------------
__global__ void fold_w1(const float* __restrict__ Wd0) {
    int i = blockIdx.x * blockDim.x + threadIdx.x;  // over 27*8*32 = 6912
    if (i >= KK * 8 * 32) return;
    int co = i & 31;
    int c  = (i >> 5) & 7;
    int k  = i >> 8;
    float s = 0.f;
#pragma unroll
    for (int j = 0; j < 4; j++) s += Wd0[k * 1024 + (8 * j + c) * 32 + co];
    g_w1f[k * 256 + c * 32 + co] = s;
}

// ---------------- compaction: count -> scan -> fill ----------------
__global__ void count_k(const unsigned char* __restrict__ mask) {
    int i = blockIdx.x * blockDim.x + threadIdx.x;
    if (i >= NV) return;
    int mode = g_maskmode;
    int c = 0;
    if (mode == 0) {
#pragma unroll
        for (int k = 0; k < KK; k++) c += (mask[(long long)k * NV + i] != 0);
    } else {
        const unsigned* m32 = (const unsigned*)mask;
#pragma unroll
        for (int k = 0; k < KK; k++) c += (m32[(long long)k * NV + i] != 0u);
    }
    g_cnt[i] = c;
}

__global__ void scan_blocks() {
    __shared__ int s[256];
    int t = threadIdx.x;
    int base = blockIdx.x * 1024 + t * 4;
    int c0 = 0, c1 = 0, c2 = 0, c3 = 0;
    if (base + 3 < NV) {
        int4 v = *(const int4*)(g_cnt + base);
        c0 = v.x; c1 = v.y; c2 = v.z; c3 = v.w;
    } else {
        if (base     < NV) c0 = g_cnt[base];
        if (base + 1 < NV) c1 = g_cnt[base + 1];
        if (base + 2 < NV) c2 = g_cnt[base + 2];
        if (base + 3 < NV) c3 = g_cnt[base + 3];
    }
    int tot = c0 + c1 + c2 + c3;
    s[t] = tot;
    __syncthreads();
#pragma unroll
    for (int off = 1; off < 256; off <<= 1) {
        int x = (t >= off) ? s[t - off] : 0;
        __syncthreads();
        s[t] += x;
        __syncthreads();
    }
    int excl = s[t] - tot;
    if (base     < NV) g_rowloc[base]     = excl;
    if (base + 1 < NV) g_rowloc[base + 1] = excl + c0;
    if (base + 2 < NV) g_rowloc[base + 2] = excl + c0 + c1;
    if (base + 3 < NV) g_rowloc[base + 3] = excl + c0 + c1 + c2;
    if (t == 255) g_bsum[blockIdx.x] = s[255];
}

__global__ void scan_tops() {  // single block, 1024 threads
    __shared__ int s[1024];
    int t = threadIdx.x;
    int v = (t < NBLK) ? g_bsum[t] : 0;
    s[t] = v;
    __syncthreads();
#pragma unroll
    for (int off = 1; off < 1024; off <<= 1) {
        int x = (t >= off) ? s[t - off] : 0;
        __syncthreads();
        s[t] += x;
        __syncthreads();
    }
    if (t < NBLK) g_bscan[t] = s[t] - v;
    if (t == 1023) g_rowoff[NV] = s[1023];
}

__global__ void finalize_rows() {
    int i = blockIdx.x * blockDim.x + threadIdx.x;
    if (i < NV) g_rowoff[i] = g_rowloc[i] + g_bscan[i >> 10];
}

__global__ void fill_entries(const unsigned char* __restrict__ mask,
                             const int* __restrict__ idx) {
    int i = blockIdx.x * blockDim.x + threadIdx.x;
    if (i >= NV) return;
    int mode = g_maskmode;
    int off = g_rowoff[i];
#pragma unroll 1
    for (int k = 0; k < KK; k++) {
        if (mask_at(mask, (long long)k * NV + i, mode)) {
            g_entries[off++] = (unsigned)idx[(long long)k * NV + i] | ((unsigned)k << 20);
        }
    }
}

// ---------------- generic sparse conv ----------------
// MODE 0: out = acc            (out stride COUT)
// MODE 1: out = xres - acc     (COUT==8, residual)
// MODE 2: out = xres[co%8]+acc (COUT==32, final add of tile(x,4))
template <int CIN, int COUT, int MODE>
__global__ void conv_sp(const float* __restrict__ in, const float* __restrict__ W,
                        const float* __restrict__ xres, float* __restrict__ out) {
    extern __shared__ float ws[];
    const int WSZ = KK * CIN * COUT;
    for (int i = threadIdx.x; i < WSZ; i += blockDim.x) ws[i] = W[i];
    __syncthreads();

    const int lane = threadIdx.x & 31;
    const int warp = threadIdx.x >> 5;
    const int GP   = 32 / COUT;               // voxels per warp (1 or 4)
    const int co   = lane & (COUT - 1);
    const int sub  = lane / COUT;
    const int gb   = lane & ~(COUT - 1);      // group base lane
    const int VPB  = (blockDim.x / 32) * GP;  // voxels per block per pass

    for (int vb = blockIdx.x * VPB; vb < NV; vb += gridDim.x * VPB) {
        int n = vb + warp * GP + sub;
        bool valid = (n < NV);
        int start = 0, cnt = 0;
        if (valid) {
            start = g_rowoff[n];
            cnt   = g_rowoff[n + 1] - start;
        }
        // warp-uniform loop bound so shuffles stay converged
        int mc = cnt;
#pragma unroll
        for (int o = 16; o; o >>= 1) mc = max(mc, __shfl_xor_sync(0xffffffffu, mc, o));

        float acc = 0.f;
        for (int j = 0; j < mc; ++j) {
            bool act = (j < cnt);
            unsigned e = act ? __ldg(g_entries + start + j) : 0u;
            int nbr = (int)(e & 0xFFFFFu);
            int k   = (int)(e >> 20);
            const float* wk = ws + k * (CIN * COUT);

            if (CIN == 8) {
                float xv = act ? __ldg(in + nbr * 8 + (lane & 7)) : 0.f;
#pragma unroll
                for (int ci = 0; ci < 8; ++ci) {
                    float bv = __shfl_sync(0xffffffffu, xv, gb + ci);
                    acc = fmaf(bv, wk[ci * COUT + co], acc);
                }
            } else if (CIN == 32 && COUT == 32) {
                float xv = act ? __ldg(in + nbr * 32 + lane) : 0.f;
#pragma unroll
                for (int ci = 0; ci < 32; ++ci) {
                    float bv = __shfl_sync(0xffffffffu, xv, ci);
                    acc = fmaf(bv, wk[ci * 32 + co], acc);
                }
            } else {  // CIN==32, COUT==8: each of 8 lanes holds a float4 chunk
                float4 xq = make_float4(0.f, 0.f, 0.f, 0.f);
                if (act) xq = *(const float4*)(in + nbr * 32 + co * 4);
                float xa[4] = {xq.x, xq.y, xq.z, xq.w};
#pragma unroll
                for (int ci = 0; ci < 32; ++ci) {
                    float bv = __shfl_sync(0xffffffffu, xa[ci & 3], gb + (ci >> 2));
                    acc = fmaf(bv, wk[ci * COUT + co], acc);
                }
            }
        }

        if (valid) {
            if (MODE == 0) {
                out[n * COUT + co] = acc;
            } else if (MODE == 1) {
                out[n * 8 + co] = xres[n * 8 + co] - acc;
            } else {
                out[n * 32 + co] = xres[n * 8 + (co & 7)] + acc;
            }
        }
    }
}

// ---------------- launcher ----------------
extern "C" void kernel_launch(void* const* d_in, const int* in_sizes, int n_in,
                              void* d_out, int out_size) {
    const float*         x    = (const float*)d_in[0];
    const int*           nidx = (const int*)d_in[1];
    const unsigned char* nmsk = (const unsigned char*)d_in[2];
    // d_in[3] = Wd0 [27,32,32] (folded), 4 = Wd1 [27,32,8], 5 = Wd2 [27,8,8]
    // 6 = Wu0 [27,8,8], 7 = Wu1 [27,8,32], 8 = Wu2 [27,32,32]
    const float* Wd0 = (const float*)d_in[3];
    const float* Wd1 = (const float*)d_in[4];
    const float* Wd2 = (const float*)d_in[5];
    const float* Wu0 = (const float*)d_in[6];
    const float* Wu1 = (const float*)d_in[7];
    const float* Wu2 = (const float*)d_in[8];
    float* outp = (float*)d_out;

    // symbol addresses for scratch
    void *p_t1, *p_t5, *p_a, *p_b, *p_w1f;
    cudaGetSymbolAddress(&p_t1, g_t1);
    cudaGetSymbolAddress(&p_t5, g_t5);
    cudaGetSymbolAddress(&p_a, g_a);
    cudaGetSymbolAddress(&p_b, g_b);
    cudaGetSymbolAddress(&p_w1f, g_w1f);
    float* t1  = (float*)p_t1;
    float* t5  = (float*)p_t5;
    float* sa  = (float*)p_a;
    float* sb  = (float*)p_b;
    float* w1f = (float*)p_w1f;

    // allow >48KB dynamic smem for the 32x32 conv (110,592 B)
    cudaFuncSetAttribute(conv_sp<32, 32, 0>,
                         cudaFuncAttributeMaxDynamicSharedMemorySize, 120000);
    cudaFuncSetAttribute(conv_sp<32, 32, 2>,
                         cudaFuncAttributeMaxDynamicSharedMemorySize, 120000);

    // mask dtype probe + prep + compaction
    detect_mask<<<1, 1024>>>(nmsk);
    fold_w1<<<27, 256>>>(Wd0);
    count_k<<<CNT_GRID, 256>>>(nmsk);
    scan_blocks<<<NBLK, 256>>>();
    scan_tops<<<1, 1024>>>();
    finalize_rows<<<CNT_GRID, 256>>>();
    fill_entries<<<CNT_GRID, 256>>>(nmsk, nidx);

    const int SM8_32  = KK * 8 * 32 * 4;    // 27648
    const int SM32_8  = KK * 32 * 8 * 4;    // 27648
    const int SM8_8   = KK * 8 * 8 * 4;     // 6912
    const int SM32_32 = KK * 32 * 32 * 4;   // 110592

    // conv chain (tile(x,4) folded into w1f; residual / final add fused)
    conv_sp<8, 32, 0><<<1184, 256, SM8_32>>>(x, w1f, nullptr, t1);     // -> t1 [N,32]
    conv_sp<32, 8, 0><<<1184, 256, SM32_8>>>(t1, Wd1, nullptr, sa);    // -> sa [N,8]
    conv_sp<8, 8, 1><<<1184, 256, SM8_8>>>(sa, Wd2, x, sb);            // sb = x - conv(sa)
    conv_sp<8, 8, 0><<<1184, 256, SM8_8>>>(sb, Wu0, nullptr, sa);      // -> sa [N,8]
    conv_sp<8, 32, 0><<<1184, 256, SM8_32>>>(sa, Wu1, nullptr, t5);    // -> t5 [N,32]
    conv_sp<32, 32, 2><<<296, 256, SM32_32>>>(t5, Wu2, x, outp);       // out = tile(x)+conv
    (void)in_sizes; (void)n_in; (void)out_size;
}